// round 4
// baseline (speedup 1.0000x reference)
#include <cuda_runtime.h>
#include <cuda_fp16.h>
#include <math.h>
#include <stdint.h>

#define NMAX 50000
#define EMAX 800000
#define KD 256
#define OD 128

// ---------------- scratch (device globals: no allocs allowed) ----------------
__device__ float  g_hp[(size_t)NMAX * OD];    // h' = X @ W   [N,128] fp32
__device__ __half g_hph[(size_t)NMAX * OD];   // h' fp16 copy (for gather pass)
__device__ float  g_edst[NMAX];
__device__ float  g_esrc[NMAX];
__device__ int    g_cnt[NMAX];
__device__ int    g_off[NMAX + 1];
__device__ int    g_pos[EMAX];                // per-edge rank within its dst
__device__ int    g_ssrc[EMAX];               // edge src sorted by dst
__device__ float  g_sscore[EMAX];             // leaky-relu'd score sorted by dst
__device__ int    g_bsum[256];
__device__ int    g_bpre[256];

// ---------------- tf32 helpers ----------------
__device__ __forceinline__ float f2tf32(float x) {
    uint32_t u;
    asm("cvt.rna.tf32.f32 %0, %1;" : "=r"(u) : "f"(x));
    return __uint_as_float(u);
}

__device__ __forceinline__ void mma_tf32(float* d, const uint32_t* a, const uint32_t* b) {
    asm volatile(
        "mma.sync.aligned.m16n8k8.row.col.f32.tf32.tf32.f32 "
        "{%0,%1,%2,%3}, {%4,%5,%6,%7}, {%8,%9}, {%0,%1,%2,%3};"
        : "+f"(d[0]), "+f"(d[1]), "+f"(d[2]), "+f"(d[3])
        : "r"(a[0]), "r"(a[1]), "r"(a[2]), "r"(a[3]), "r"(b[0]), "r"(b[1]));
}

// ---------------- GEMM: [M,256] x [256,128] -> [M,128], 3xTF32 tensor core ----------------
// BM=128, BN=128(full), BK=16. 256 threads = 8 warps in 4x2; warp tile 32x64.
#define APAD 20    // As row stride (floats): conflict-free frag reads
#define BPAD 136   // Bs row stride (floats): conflict-free frag reads

__global__ __launch_bounds__(256, 2)
void k_gemm(const float* __restrict__ A, const float* __restrict__ W,
            float* __restrict__ C, __half* __restrict__ Ch, int M) {
    __shared__ float As_hi[128 * APAD];
    __shared__ float As_lo[128 * APAD];
    __shared__ float Bs_hi[16 * BPAD];
    __shared__ float Bs_lo[16 * BPAD];

    const int tid  = threadIdx.x;
    const int lane = tid & 31;
    const int warp = tid >> 5;
    const int wm = warp >> 1;        // 0..3
    const int wn = warp & 1;         // 0..1
    const int m0 = blockIdx.x * 128;
    const int g = lane >> 2;         // 0..7
    const int t = lane & 3;          // 0..3

    float acc[2][8][4];
#pragma unroll
    for (int mt = 0; mt < 2; mt++)
#pragma unroll
        for (int nt = 0; nt < 8; nt++)
#pragma unroll
            for (int c = 0; c < 4; c++) acc[mt][nt][c] = 0.f;

    int a_r[2], a_c[2], b_r[2], b_c[2];
#pragma unroll
    for (int s = 0; s < 2; s++) {
        int idx = tid + s * 256;         // 0..511
        a_r[s] = idx >> 2;               // 0..127
        a_c[s] = (idx & 3) * 4;          // 0,4,8,12
        b_r[s] = idx >> 5;               // 0..15
        b_c[s] = (idx & 31) * 4;         // 0..124
    }

    float4 pa[2], pb[2];
#pragma unroll
    for (int s = 0; s < 2; s++) {
        int gr = m0 + a_r[s];
        pa[s] = (gr < M) ? *(const float4*)(A + (size_t)gr * KD + a_c[s])
                         : make_float4(0.f, 0.f, 0.f, 0.f);
        pb[s] = *(const float4*)(W + (size_t)b_r[s] * OD + b_c[s]);
    }

    for (int kt = 0; kt < 16; kt++) {
#pragma unroll
        for (int s = 0; s < 2; s++) {
            float4 v = pa[s];
            float4 hi, lo;
            hi.x = f2tf32(v.x); lo.x = f2tf32(v.x - hi.x);
            hi.y = f2tf32(v.y); lo.y = f2tf32(v.y - hi.y);
            hi.z = f2tf32(v.z); lo.z = f2tf32(v.z - hi.z);
            hi.w = f2tf32(v.w); lo.w = f2tf32(v.w - hi.w);
            *(float4*)&As_hi[a_r[s] * APAD + a_c[s]] = hi;
            *(float4*)&As_lo[a_r[s] * APAD + a_c[s]] = lo;
            v = pb[s];
            hi.x = f2tf32(v.x); lo.x = f2tf32(v.x - hi.x);
            hi.y = f2tf32(v.y); lo.y = f2tf32(v.y - hi.y);
            hi.z = f2tf32(v.z); lo.z = f2tf32(v.z - hi.z);
            hi.w = f2tf32(v.w); lo.w = f2tf32(v.w - hi.w);
            *(float4*)&Bs_hi[b_r[s] * BPAD + b_c[s]] = hi;
            *(float4*)&Bs_lo[b_r[s] * BPAD + b_c[s]] = lo;
        }
        __syncthreads();

        if (kt < 15) {
            int k0 = (kt + 1) * 16;
#pragma unroll
            for (int s = 0; s < 2; s++) {
                int gr = m0 + a_r[s];
                pa[s] = (gr < M) ? *(const float4*)(A + (size_t)gr * KD + k0 + a_c[s])
                                 : make_float4(0.f, 0.f, 0.f, 0.f);
                pb[s] = *(const float4*)(W + (size_t)(k0 + b_r[s]) * OD + b_c[s]);
            }
        }

#pragma unroll
        for (int ks = 0; ks < 2; ks++) {
            int ko = ks * 8;
            uint32_t ah[2][4], al[2][4];
#pragma unroll
            for (int mt = 0; mt < 2; mt++) {
                int rm = wm * 32 + mt * 16;
                ah[mt][0] = __float_as_uint(As_hi[(rm + g) * APAD + ko + t]);
                ah[mt][1] = __float_as_uint(As_hi[(rm + g + 8) * APAD + ko + t]);
                ah[mt][2] = __float_as_uint(As_hi[(rm + g) * APAD + ko + t + 4]);
                ah[mt][3] = __float_as_uint(As_hi[(rm + g + 8) * APAD + ko + t + 4]);
                al[mt][0] = __float_as_uint(As_lo[(rm + g) * APAD + ko + t]);
                al[mt][1] = __float_as_uint(As_lo[(rm + g + 8) * APAD + ko + t]);
                al[mt][2] = __float_as_uint(As_lo[(rm + g) * APAD + ko + t + 4]);
                al[mt][3] = __float_as_uint(As_lo[(rm + g + 8) * APAD + ko + t + 4]);
            }
#pragma unroll
            for (int nt = 0; nt < 8; nt++) {
                int nc = wn * 64 + nt * 8 + g;
                uint32_t bh[2], bl[2];
                bh[0] = __float_as_uint(Bs_hi[(ko + t) * BPAD + nc]);
                bh[1] = __float_as_uint(Bs_hi[(ko + t + 4) * BPAD + nc]);
                bl[0] = __float_as_uint(Bs_lo[(ko + t) * BPAD + nc]);
                bl[1] = __float_as_uint(Bs_lo[(ko + t + 4) * BPAD + nc]);
#pragma unroll
                for (int mt = 0; mt < 2; mt++) {
                    mma_tf32(acc[mt][nt], ah[mt], bh);   // hi*hi
                    mma_tf32(acc[mt][nt], al[mt], bh);   // lo*hi
                    mma_tf32(acc[mt][nt], ah[mt], bl);   // hi*lo
                }
            }
        }
        __syncthreads();
    }

    // epilogue: fp32 store + fp16 shadow store
#pragma unroll
    for (int mt = 0; mt < 2; mt++) {
#pragma unroll
        for (int nt = 0; nt < 8; nt++) {
            int row = m0 + wm * 32 + mt * 16 + g;
            int col = wn * 64 + nt * 8 + 2 * t;
            if (row < M) {
                *(float2*)(C + (size_t)row * OD + col) = make_float2(acc[mt][nt][0], acc[mt][nt][1]);
                *(__half2*)(Ch + (size_t)row * OD + col) =
                    __floats2half2_rn(acc[mt][nt][0], acc[mt][nt][1]);
            }
            if (row + 8 < M) {
                *(float2*)(C + (size_t)(row + 8) * OD + col) = make_float2(acc[mt][nt][2], acc[mt][nt][3]);
                *(__half2*)(Ch + (size_t)(row + 8) * OD + col) =
                    __floats2half2_rn(acc[mt][nt][2], acc[mt][nt][3]);
            }
        }
    }
}

// ---------------- per-node attention logits: e = h'.a + b (+ zero cnt) ----------------
__global__ void k_node_e(const float* __restrict__ hp,
                         const float* __restrict__ a_dst, const float* __restrict__ b_dst,
                         const float* __restrict__ a_src, const float* __restrict__ b_src,
                         float* __restrict__ edst, float* __restrict__ esrc,
                         int* __restrict__ cnt, int n) {
    int warp = (blockIdx.x * blockDim.x + threadIdx.x) >> 5;
    int lane = threadIdx.x & 31;
    if (warp >= n) return;
    float4 h = *(const float4*)(hp + (size_t)warp * OD + lane * 4);
    float4 ad = *(const float4*)(a_dst + lane * 4);
    float4 as = *(const float4*)(a_src + lane * 4);
    float sd = h.x * ad.x + h.y * ad.y + h.z * ad.z + h.w * ad.w;
    float ss = h.x * as.x + h.y * as.y + h.z * as.z + h.w * as.w;
#pragma unroll
    for (int d = 16; d; d >>= 1) {
        sd += __shfl_xor_sync(0xffffffffu, sd, d);
        ss += __shfl_xor_sync(0xffffffffu, ss, d);
    }
    if (lane == 0) {
        edst[warp] = sd + b_dst[0];
        esrc[warp] = ss + b_src[0];
        cnt[warp] = 0;
    }
}

// ---------------- CSR build: pos pass (the ONLY atomic pass) ----------------
__global__ void k_pos(const int* __restrict__ dst, int e,
                      int* __restrict__ cnt, int* __restrict__ pos) {
    int i = (blockIdx.x * blockDim.x + threadIdx.x) * 4;
    if (i + 3 < e) {
        int4 d = *(const int4*)(dst + i);
        int4 p;
        p.x = atomicAdd(&cnt[d.x], 1);
        p.y = atomicAdd(&cnt[d.y], 1);
        p.z = atomicAdd(&cnt[d.z], 1);
        p.w = atomicAdd(&cnt[d.w], 1);
        *(int4*)(pos + i) = p;
    } else {
        for (int j = i; j < e; j++) pos[j] = atomicAdd(&cnt[dst[j]], 1);
    }
}

// ---- hierarchical exclusive scan: scan1 (per 256-block) -> scan2 (block sums) -> scan3 (add) ----
__global__ __launch_bounds__(256)
void k_scan1(const int* __restrict__ cnt, int n, int* __restrict__ off) {
    __shared__ int ws[8];
    int tid = threadIdx.x, lane = tid & 31, w = tid >> 5;
    int i = blockIdx.x * 256 + tid;
    int v = (i < n) ? cnt[i] : 0;
    int x = v;
#pragma unroll
    for (int d = 1; d < 32; d <<= 1) {
        int y = __shfl_up_sync(0xffffffffu, x, d);
        if (lane >= d) x += y;
    }
    if (lane == 31) ws[w] = x;
    __syncthreads();
    if (tid < 8) {
        int s = ws[tid];
#pragma unroll
        for (int d = 1; d < 8; d <<= 1) {
            int y = __shfl_up_sync(0xffu, s, d);
            if (tid >= d) s += y;
        }
        ws[tid] = s;
    }
    __syncthreads();
    int incl = x + (w ? ws[w - 1] : 0);
    if (i < n) off[i] = incl - v;
    if (tid == 255) g_bsum[blockIdx.x] = incl;
}

__global__ __launch_bounds__(256)
void k_scan2(int nb, int n, int* __restrict__ off) {
    __shared__ int ws[8];
    int tid = threadIdx.x, lane = tid & 31, w = tid >> 5;
    int v = (tid < nb) ? g_bsum[tid] : 0;
    int x = v;
#pragma unroll
    for (int d = 1; d < 32; d <<= 1) {
        int y = __shfl_up_sync(0xffffffffu, x, d);
        if (lane >= d) x += y;
    }
    if (lane == 31) ws[w] = x;
    __syncthreads();
    if (tid < 8) {
        int s = ws[tid];
#pragma unroll
        for (int d = 1; d < 8; d <<= 1) {
            int y = __shfl_up_sync(0xffu, s, d);
            if (tid >= d) s += y;
        }
        ws[tid] = s;
    }
    __syncthreads();
    int incl = x + (w ? ws[w - 1] : 0);
    g_bpre[tid] = incl - v;
    if (tid == 255) off[n] = incl;
}

__global__ void k_scan3(int n, int* __restrict__ off) {
    int i = blockIdx.x * 256 + threadIdx.x;
    if (i < n) off[i] += g_bpre[blockIdx.x];
}

// ---------------- atomic-free scatter: p = off[dst] + pos ----------------
__global__ void k_scatter(const int* __restrict__ src, const int* __restrict__ dst, int e,
                          const int* __restrict__ off, const int* __restrict__ pos,
                          const float* __restrict__ edst, const float* __restrict__ esrc,
                          int* __restrict__ ssrc, float* __restrict__ sscore) {
    int i = blockIdx.x * blockDim.x + threadIdx.x;
    if (i >= e) return;
    int d = dst[i], s = src[i];
    int p = off[d] + pos[i];
    float sc = edst[d] + esrc[s];
    ssrc[p] = s;
    sscore[p] = (sc >= 0.f) ? sc : 0.2f * sc;
}

// ---------------- warp-per-dst softmax + fp16 gather aggregation + ELU ----------------
__global__ __launch_bounds__(256)
void k_agg(const int* __restrict__ off, const int* __restrict__ ssrc,
           const float* __restrict__ sscore, const __half* __restrict__ hph,
           const float* __restrict__ bias, float* __restrict__ out, int n) {
    int warp = (blockIdx.x * blockDim.x + threadIdx.x) >> 5;
    int lane = threadIdx.x & 31;
    if (warp >= n) return;
    int s = off[warp], e = off[warp + 1];

    float m = -INFINITY;
    for (int i = s + lane; i < e; i += 32) m = fmaxf(m, sscore[i]);
#pragma unroll
    for (int d = 16; d; d >>= 1) m = fmaxf(m, __shfl_xor_sync(0xffffffffu, m, d));

    float sum = 0.f;
    for (int i = s + lane; i < e; i += 32) sum += __expf(sscore[i] - m);
#pragma unroll
    for (int d = 16; d; d >>= 1) sum += __shfl_xor_sync(0xffffffffu, sum, d);
    float inv = 1.0f / fmaxf(sum, 1e-12f);

    float4 acc = make_float4(0.f, 0.f, 0.f, 0.f);
    int i = s;
    for (; i + 1 < e; i += 2) {
        int s0 = ssrc[i], s1 = ssrc[i + 1];
        float w0 = __expf(sscore[i] - m) * inv;
        float w1 = __expf(sscore[i + 1] - m) * inv;
        uint2 r0 = *(const uint2*)(hph + (size_t)s0 * OD + lane * 4);
        uint2 r1 = *(const uint2*)(hph + (size_t)s1 * OD + lane * 4);
        float2 a0 = __half22float2(*reinterpret_cast<__half2*>(&r0.x));
        float2 b0 = __half22float2(*reinterpret_cast<__half2*>(&r0.y));
        float2 a1 = __half22float2(*reinterpret_cast<__half2*>(&r1.x));
        float2 b1 = __half22float2(*reinterpret_cast<__half2*>(&r1.y));
        acc.x += w0 * a0.x + w1 * a1.x;
        acc.y += w0 * a0.y + w1 * a1.y;
        acc.z += w0 * b0.x + w1 * b1.x;
        acc.w += w0 * b0.y + w1 * b1.y;
    }
    if (i < e) {
        int s0 = ssrc[i];
        float w0 = __expf(sscore[i] - m) * inv;
        uint2 r0 = *(const uint2*)(hph + (size_t)s0 * OD + lane * 4);
        float2 a0 = __half22float2(*reinterpret_cast<__half2*>(&r0.x));
        float2 b0 = __half22float2(*reinterpret_cast<__half2*>(&r0.y));
        acc.x += w0 * a0.x; acc.y += w0 * a0.y; acc.z += w0 * b0.x; acc.w += w0 * b0.y;
    }

    float4 b = *(const float4*)(bias + lane * 4);
    acc.x += b.x; acc.y += b.y; acc.z += b.z; acc.w += b.w;
    acc.x = acc.x > 0.f ? acc.x : expm1f(acc.x);
    acc.y = acc.y > 0.f ? acc.y : expm1f(acc.y);
    acc.z = acc.z > 0.f ? acc.z : expm1f(acc.z);
    acc.w = acc.w > 0.f ? acc.w : expm1f(acc.w);
    *(float4*)(out + (size_t)warp * OD + lane * 4) = acc;
}

// ---------------- launch ----------------
extern "C" void kernel_launch(void* const* d_in, const int* in_sizes, int n_in,
                              void* d_out, int out_size) {
    const float* inputs = (const float*)d_in[0];
    const int*   esrc   = (const int*)d_in[1];
    const int*   edst   = (const int*)d_in[2];
    const float* W      = (const float*)d_in[3];
    const float* a_dst  = (const float*)d_in[4];
    const float* b_dst  = (const float*)d_in[5];
    const float* a_src  = (const float*)d_in[6];
    const float* b_src  = (const float*)d_in[7];
    const float* obias  = (const float*)d_in[8];
    float* out = (float*)d_out;

    int n = in_sizes[0] / KD;
    int e = in_sizes[1];
    int nb = (n + 255) / 256;

    float *hp, *pedst, *pesrc, *pscore;
    __half* hph;
    int *pcnt, *poff, *ppos, *pssrc;
    cudaGetSymbolAddress((void**)&hp, g_hp);
    cudaGetSymbolAddress((void**)&hph, g_hph);
    cudaGetSymbolAddress((void**)&pedst, g_edst);
    cudaGetSymbolAddress((void**)&pesrc, g_esrc);
    cudaGetSymbolAddress((void**)&pcnt, g_cnt);
    cudaGetSymbolAddress((void**)&poff, g_off);
    cudaGetSymbolAddress((void**)&ppos, g_pos);
    cudaGetSymbolAddress((void**)&pssrc, g_ssrc);
    cudaGetSymbolAddress((void**)&pscore, g_sscore);

    k_gemm<<<(n + 127) / 128, 256>>>(inputs, W, hp, hph, n);
    k_node_e<<<(n * 32 + 255) / 256, 256>>>(hp, a_dst, b_dst, a_src, b_src, pedst, pesrc, pcnt, n);
    k_pos<<<((e + 3) / 4 + 255) / 256, 256>>>(edst, e, pcnt, ppos);
    k_scan1<<<nb, 256>>>(pcnt, n, poff);
    k_scan2<<<1, 256>>>(nb, n, poff);
    k_scan3<<<nb, 256>>>(n, poff);
    k_scatter<<<(e + 255) / 256, 256>>>(esrc, edst, e, poff, ppos, pedst, pesrc, pssrc, pscore);
    k_agg<<<(n * 32 + 255) / 256, 256>>>(poff, pssrc, pscore, hph, obias, out, n);
}